// round 5
// baseline (speedup 1.0000x reference)
#include <cuda_runtime.h>
#include <cuda_bf16.h>
#include <cstdint>

// CIF: continuous integrate-and-fire. B=32, T=2000, H=512, L=256, thresh=0.95
//
// Scan kernel (1 CTA x 1024 threads):
//   - warp w computes row w's sum in double (shfl reduce) -> scale
//   - staged tiles of scaled alphas transposed to smem [t][b] (pad 33)
//   - warp 0: lane b runs row b's full fp32 recurrence (all 32 rows in one
//     instruction stream); fire records (fpos, rem, cur) written branchlessly
//     to smem [k][b] at idx=min(nf,256) (overwrite until nf advances)
//   - coalesced flush to global [B][L]
// Gather kernel (grid (L,B) x 128): interior frame weights recomputed as
//   alphas[t]*scale (bit-identical FMUL); segment-end fire frame uses cur[k];
//   previous-fire frame uses rem[k-1].

#define CIF_B 32
#define CIF_T 2000
#define CIF_H 512
#define CIF_L 256
#define CIF_THRESH 0.95f

#define TILE 512
#define NTILE 4            // 4*512 = 2048 >= 2000 (zero padded)

// dyn smem layout (floats):
#define O_A    0                       // TILE*33 = 16896
#define O_FP   16896                   // 257*33 = 8481 (int)
#define O_RM   (O_FP + 8481)           // 8481
#define O_CUR  (O_RM + 8481)           // 8481
#define O_SC   (O_CUR + 8481)          // 32
#define SMEM_FLOATS (O_SC + 32)        // 42371 -> 169484 bytes

// Scratch (allocation-free contract)
__device__ int   g_fpos[CIF_B * CIF_L];
__device__ float g_rem [CIF_B * CIF_L];
__device__ float g_cur [CIF_B * CIF_L];
__device__ float g_scale[CIF_B];
__device__ int   g_nf[CIF_B];

// ---------------------------------------------------------------------------
__global__ __launch_bounds__(1024, 1)
void cif_scan_kernel(const float* __restrict__ alphas,
                     const int* __restrict__ target_lengths)
{
    extern __shared__ float sm[];
    float* s_a   = sm + O_A;
    int*   s_fp  = (int*)(sm + O_FP);
    float* s_rm  = sm + O_RM;
    float* s_cur = sm + O_CUR;
    float* s_sc  = sm + O_SC;

    const int tid  = threadIdx.x;
    const int wid  = tid >> 5;
    const int lane = tid & 31;

    // --- row sums: warp w handles row w, double precision, shfl reduce ---
    {
        const float* arow = alphas + wid * CIF_T;
        double a0 = 0.0, a1 = 0.0;
        for (int t = lane; t < CIF_T; t += 64) {
            a0 += (double)arow[t];
            if (t + 32 < CIF_T) a1 += (double)arow[t + 32];
        }
        double acc = a0 + a1;
        #pragma unroll
        for (int off = 16; off; off >>= 1)
            acc += __shfl_down_sync(0xffffffffu, acc, off);
        if (lane == 0) {
            float sc = (float)target_lengths[wid] / (float)acc;
            s_sc[wid] = sc;
            g_scale[wid] = sc;
        }
    }
    __syncthreads();

    // --- tiled stage + lane-parallel scan (warp 0; lane = batch row) ---
    float integ = 0.0f;
    int   nf    = 0;
    for (int tile = 0; tile < NTILE; ++tile) {
        const int tbase = tile * TILE;
        // stage: transpose scaled alphas into s_a[tt*33 + b]
        #pragma unroll
        for (int p = 0; p < (TILE * CIF_B) / 1024; ++p) {
            int e  = p * 1024 + tid;
            int tt = e & (TILE - 1);
            int b  = e >> 9;                      // TILE = 512
            int t  = tbase + tt;
            float v = (t < CIF_T) ? alphas[b * CIF_T + t] * s_sc[b] : 0.0f;
            s_a[tt * 33 + b] = v;
        }
        __syncthreads();

        if (wid == 0) {
            #pragma unroll 8
            for (int j = 0; j < TILE; ++j) {
                float a    = s_a[j * 33 + lane];
                float i2   = integ + a;               // fl(integ + alpha)
                bool  fire = (i2 >= CIF_THRESH);
                float cur  = 1.0f - integ;            // dist_completion
                float rm   = a - cur;                 // remainds
                int   idx  = nf < CIF_L ? nf : CIF_L; // row 256 = scratch
                s_fp [idx * 33 + lane] = tbase + j;
                s_rm [idx * 33 + lane] = rm;
                s_cur[idx * 33 + lane] = cur;
                integ = fire ? (i2 - 1.0f) : i2;      // Sterbenz-exact subtract
                nf   += fire ? 1 : 0;
            }
        }
        __syncthreads();
    }
    if (wid == 0)
        g_nf[lane] = nf;

    // --- coalesced flush: [k][b] smem -> [b][k] global ---
    #pragma unroll
    for (int p = 0; p < (CIF_B * CIF_L) / 1024; ++p) {
        int e = p * 1024 + tid;
        int k = e & (CIF_L - 1);
        int b = e >> 8;
        g_fpos[b * CIF_L + k] = s_fp [k * 33 + b];
        g_rem [b * CIF_L + k] = s_rm [k * 33 + b];
        g_cur [b * CIF_L + k] = s_cur[k * 33 + b];
    }
}

// ---------------------------------------------------------------------------
// Gather: grid (L, B) x 128 threads, one float4 per thread over H=512
// ---------------------------------------------------------------------------
__global__ __launch_bounds__(128, 16)
void cif_gather_kernel(const float* __restrict__ hidden,
                       const float* __restrict__ alphas,
                       float* __restrict__ out)
{
    const int k   = blockIdx.x;
    const int b   = blockIdx.y;
    const int tid = threadIdx.x;
    const int HS  = CIF_H / 4;

    float4* out4 = reinterpret_cast<float4*>(out + ((size_t)(b * CIF_L + k)) * CIF_H) + tid;

    int nf = g_nf[b];
    nf = nf < CIF_L ? nf : CIF_L;
    if (k >= nf) {
        *out4 = make_float4(0.f, 0.f, 0.f, 0.f);
        return;
    }

    const float   scale = g_scale[b];
    const int     te    = g_fpos[b * CIF_L + k];
    const float*  arow  = alphas + b * CIF_T;
    const float4* h4    = reinterpret_cast<const float4*>(hidden + (size_t)b * CIF_T * CIF_H) + tid;

    float4 accv;
    int t0;
    if (k == 0) {
        t0 = 0;
        accv = make_float4(0.f, 0.f, 0.f, 0.f);
    } else {
        const int   ts = g_fpos[b * CIF_L + k - 1];
        const float wt = g_rem[b * CIF_L + k - 1];
        float4 hv = __ldg(h4 + (size_t)ts * HS);
        accv = make_float4(wt * hv.x, wt * hv.y, wt * hv.z, wt * hv.w);
        t0 = ts + 1;
    }

    // interior frames: weight = alphas[t] * scale (bit-identical to scan's a)
    #pragma unroll 4
    for (int t = t0; t < te; ++t) {
        float  w  = __ldg(arow + t) * scale;
        float4 hv = __ldg(h4 + (size_t)t * HS);
        accv.x = fmaf(w, hv.x, accv.x);
        accv.y = fmaf(w, hv.y, accv.y);
        accv.z = fmaf(w, hv.z, accv.z);
        accv.w = fmaf(w, hv.w, accv.w);
    }
    // segment-end fire frame: weight = cur
    {
        float  wc = g_cur[b * CIF_L + k];
        float4 hv = __ldg(h4 + (size_t)te * HS);
        accv.x = fmaf(wc, hv.x, accv.x);
        accv.y = fmaf(wc, hv.y, accv.y);
        accv.z = fmaf(wc, hv.z, accv.z);
        accv.w = fmaf(wc, hv.w, accv.w);
    }
    *out4 = accv;
}

// ---------------------------------------------------------------------------
extern "C" void kernel_launch(void* const* d_in, const int* in_sizes, int n_in,
                              void* d_out, int out_size)
{
    const float* hidden = (const float*)d_in[0];
    const float* alphas = (const float*)d_in[1];
    const int*   tlen   = (const int*)d_in[2];
    float* out = (float*)d_out;

    static bool attr_set = false;
    if (!attr_set) {
        cudaFuncSetAttribute(cif_scan_kernel,
                             cudaFuncAttributeMaxDynamicSharedMemorySize,
                             SMEM_FLOATS * (int)sizeof(float));
        attr_set = true;
    }

    cif_scan_kernel<<<1, 1024, SMEM_FLOATS * sizeof(float)>>>(alphas, tlen);
    dim3 grid(CIF_L, CIF_B);
    cif_gather_kernel<<<grid, 128>>>(hidden, alphas, out);
}

// round 7
// speedup vs baseline: 2.1109x; 2.1109x over previous
#include <cuda_runtime.h>
#include <cuda_bf16.h>
#include <cstdint>

// CIF: continuous integrate-and-fire. B=32, T=2000, H=512, L=256, thresh=0.95
//
// Scan (32 CTAs x 256 threads, one per batch row):
//   1. double-precision row sum -> fp32 scale
//   2. serial minimal chain on thread 0: ONLY integ (4 asm instrs/step:
//      add/setp/add/selp), alphas fed by float4 LDS; checkpoint integ every 32
//   3. replay pass 1: 63 threads re-run their chunk bit-exactly, count fires
//   4. thread 0 prefix-sums chunk counts -> token offsets
//   5. replay pass 2: write fpos/rem/cur at offset+local (bit-exact values)
// Gather (grid (L,B) x 128): interior weights = alphas[t]*scale (bit-identical
//   FMUL), segment-end fire frame uses cur[k], carry frame uses rem[k-1].

#define CIF_B 32
#define CIF_T 2000
#define CIF_H 512
#define CIF_L 256
#define CIF_THRESH 0.95f

#define CHUNK 32
#define NCHUNK 63                 // 63*32 = 2016 >= 2000 (zero-padded)
#define T_PAD (NCHUNK * CHUNK)

// Scratch (allocation-free contract)
__device__ int   g_fpos[CIF_B * CIF_L];
__device__ float g_rem [CIF_B * CIF_L];
__device__ float g_cur [CIF_B * CIF_L];
__device__ float g_scale[CIF_B];
__device__ int   g_nf[CIF_B];

// minimal CIF step: 4 instructions, chain add->setp/selp (pred-as-data)
__device__ __forceinline__ void cif_step_min(float a, float& integ)
{
    float i2, sub;
    asm("{\n\t"
        ".reg .pred p;\n\t"
        "add.f32 %0, %2, %3;\n\t"               // i2 = integ + a
        "setp.ge.f32 p, %0, 0f3F733333;\n\t"    // fire = i2 >= 0.95f
        "add.f32 %1, %0, 0fBF800000;\n\t"       // sub = i2 - 1.0f (Sterbenz-exact)
        "selp.f32 %2, %1, %0, p;\n\t"           // integ = fire ? sub : i2
        "}"
        : "=f"(i2), "=f"(sub), "+f"(integ)
        : "f"(a));
}

// ---------------------------------------------------------------------------
// Kernel A: rescale + minimal serial scan + two-pass bit-exact reconstruction
// ---------------------------------------------------------------------------
__global__ __launch_bounds__(256, 1)
void cif_scan_kernel(const float* __restrict__ alphas,
                     const int* __restrict__ target_lengths)
{
    __shared__ __align__(16) float s_a[T_PAD];   // scaled alphas, zero-padded
    __shared__ float  s_i0[NCHUNK];              // chunk-start integ
    __shared__ int    s_cnt[NCHUNK];             // fires per chunk
    __shared__ int    s_off[NCHUNK];             // token offset per chunk
    __shared__ int    s_fp[CIF_L];
    __shared__ float  s_rm[CIF_L];
    __shared__ float  s_cur[CIF_L];
    __shared__ double s_red[256];
    __shared__ float  s_scale;
    __shared__ int    s_nf;

    const int b   = blockIdx.x;
    const int tid = threadIdx.x;
    const float* arow = alphas + b * CIF_T;

    // --- deterministic double-precision row sum ---
    double acc = 0.0;
    for (int t = tid; t < CIF_T; t += 256)
        acc += (double)arow[t];
    s_red[tid] = acc;
    __syncthreads();
    for (int off = 128; off > 0; off >>= 1) {
        if (tid < off) s_red[tid] += s_red[tid + off];
        __syncthreads();
    }
    if (tid == 0) {
        float sc = (float)target_lengths[b] / (float)s_red[0];
        s_scale = sc;
        g_scale[b] = sc;
    }
    __syncthreads();

    // --- stage scaled alphas (fp32 mul, like reference); zero pad ---
    const float scale = s_scale;
    for (int t = tid; t < T_PAD; t += 256)
        s_a[t] = (t < CIF_T) ? arow[t] * scale : 0.0f;
    __syncthreads();

    // --- serial minimal chain: only integ; checkpoint every 32 steps ---
    if (tid == 0) {
        float integ = 0.0f;
        const float4* a4 = reinterpret_cast<const float4*>(s_a);
        #pragma unroll 1
        for (int c = 0; c < NCHUNK; ++c) {
            s_i0[c] = integ;
            #pragma unroll
            for (int q = 0; q < CHUNK / 4; ++q) {
                float4 av = a4[c * (CHUNK / 4) + q];
                cif_step_min(av.x, integ);
                cif_step_min(av.y, integ);
                cif_step_min(av.z, integ);
                cif_step_min(av.w, integ);
            }
        }
    }
    __syncthreads();

    // --- replay pass 1: count fires per chunk (bit-exact) ---
    if (tid < NCHUNK) {
        float integ = s_i0[tid];
        int cnt = 0;
        const int tbase = tid * CHUNK;
        #pragma unroll
        for (int j = 0; j < CHUNK; ++j) {
            float a    = s_a[tbase + j];
            float i2   = integ + a;
            bool  fire = (i2 >= CIF_THRESH);
            integ = fire ? (i2 - 1.0f) : i2;
            cnt  += fire ? 1 : 0;
        }
        s_cnt[tid] = cnt;
    }
    __syncthreads();

    // --- prefix sum over 63 chunks ---
    if (tid == 0) {
        int accn = 0;
        #pragma unroll
        for (int c = 0; c < NCHUNK; ++c) {
            s_off[c] = accn;
            accn += s_cnt[c];
        }
        s_nf = accn;
        g_nf[b] = accn;
    }
    __syncthreads();

    // --- replay pass 2: emit records (bit-exact values) ---
    if (tid < NCHUNK) {
        float integ = s_i0[tid];
        int k = s_off[tid];
        const int tbase = tid * CHUNK;
        #pragma unroll
        for (int j = 0; j < CHUNK; ++j) {
            float a    = s_a[tbase + j];
            float i2   = integ + a;
            bool  fire = (i2 >= CIF_THRESH);
            float cur  = 1.0f - integ;            // dist_completion (old integ)
            if (fire) {
                if (k < CIF_L) {
                    s_fp[k]  = tbase + j;
                    s_rm[k]  = a - cur;           // remainds
                    s_cur[k] = cur;
                }
                k++;
            }
            integ = fire ? (i2 - 1.0f) : i2;
        }
    }
    __syncthreads();

    // --- flush valid records ---
    int nf_tot = s_nf < CIF_L ? s_nf : CIF_L;
    if (tid < nf_tot) {
        g_fpos[b * CIF_L + tid] = s_fp[tid];
        g_rem [b * CIF_L + tid] = s_rm[tid];
        g_cur [b * CIF_L + tid] = s_cur[tid];
    }
}

// ---------------------------------------------------------------------------
// Kernel B: segmented weighted gather (grid (L,B), 128 threads; float4/thread)
// ---------------------------------------------------------------------------
__global__ __launch_bounds__(128, 12)
void cif_gather_kernel(const float* __restrict__ hidden,
                       const float* __restrict__ alphas,
                       float* __restrict__ out)
{
    const int k   = blockIdx.x;
    const int b   = blockIdx.y;
    const int tid = threadIdx.x;
    const int HS  = CIF_H / 4;

    float4* out4 = reinterpret_cast<float4*>(out + ((size_t)(b * CIF_L + k)) * CIF_H) + tid;

    int nf = g_nf[b];
    nf = nf < CIF_L ? nf : CIF_L;
    if (k >= nf) {
        *out4 = make_float4(0.f, 0.f, 0.f, 0.f);
        return;
    }

    const float   scale = g_scale[b];
    const int     te    = g_fpos[b * CIF_L + k];
    const float*  arow  = alphas + b * CIF_T;
    const float4* h4    = reinterpret_cast<const float4*>(hidden + (size_t)b * CIF_T * CIF_H) + tid;

    float4 accv;
    int t0;
    if (k == 0) {
        t0 = 0;
        accv = make_float4(0.f, 0.f, 0.f, 0.f);
    } else {
        const int   ts = g_fpos[b * CIF_L + k - 1];
        const float wt = g_rem[b * CIF_L + k - 1];
        float4 hv = __ldg(h4 + (size_t)ts * HS);
        accv = make_float4(wt * hv.x, wt * hv.y, wt * hv.z, wt * hv.w);
        t0 = ts + 1;
    }

    // interior frames t0 .. te-1 : weight = alphas[t]*scale (bit-identical)
    int t = t0;
    for (; t + 4 <= te; t += 4) {
        float w0 = __ldg(arow + t)     * scale;
        float w1 = __ldg(arow + t + 1) * scale;
        float w2 = __ldg(arow + t + 2) * scale;
        float w3 = __ldg(arow + t + 3) * scale;
        float4 h0 = __ldg(h4 + (size_t)(t    ) * HS);
        float4 h1 = __ldg(h4 + (size_t)(t + 1) * HS);
        float4 h2 = __ldg(h4 + (size_t)(t + 2) * HS);
        float4 h3 = __ldg(h4 + (size_t)(t + 3) * HS);
        accv.x = fmaf(w0, h0.x, accv.x); accv.y = fmaf(w0, h0.y, accv.y);
        accv.z = fmaf(w0, h0.z, accv.z); accv.w = fmaf(w0, h0.w, accv.w);
        accv.x = fmaf(w1, h1.x, accv.x); accv.y = fmaf(w1, h1.y, accv.y);
        accv.z = fmaf(w1, h1.z, accv.z); accv.w = fmaf(w1, h1.w, accv.w);
        accv.x = fmaf(w2, h2.x, accv.x); accv.y = fmaf(w2, h2.y, accv.y);
        accv.z = fmaf(w2, h2.z, accv.z); accv.w = fmaf(w2, h2.w, accv.w);
        accv.x = fmaf(w3, h3.x, accv.x); accv.y = fmaf(w3, h3.y, accv.y);
        accv.z = fmaf(w3, h3.z, accv.z); accv.w = fmaf(w3, h3.w, accv.w);
    }
    for (; t < te; ++t) {
        float  w  = __ldg(arow + t) * scale;
        float4 hv = __ldg(h4 + (size_t)t * HS);
        accv.x = fmaf(w, hv.x, accv.x);
        accv.y = fmaf(w, hv.y, accv.y);
        accv.z = fmaf(w, hv.z, accv.z);
        accv.w = fmaf(w, hv.w, accv.w);
    }
    // segment-end fire frame: weight = cur
    {
        float  wc = g_cur[b * CIF_L + k];
        float4 hv = __ldg(h4 + (size_t)te * HS);
        accv.x = fmaf(wc, hv.x, accv.x);
        accv.y = fmaf(wc, hv.y, accv.y);
        accv.z = fmaf(wc, hv.z, accv.z);
        accv.w = fmaf(wc, hv.w, accv.w);
    }
    *out4 = accv;
}

// ---------------------------------------------------------------------------
extern "C" void kernel_launch(void* const* d_in, const int* in_sizes, int n_in,
                              void* d_out, int out_size)
{
    const float* hidden = (const float*)d_in[0];
    const float* alphas = (const float*)d_in[1];
    const int*   tlen   = (const int*)d_in[2];
    float* out = (float*)d_out;

    cif_scan_kernel<<<CIF_B, 256>>>(alphas, tlen);
    dim3 grid(CIF_L, CIF_B);
    cif_gather_kernel<<<grid, 128>>>(hidden, alphas, out);
}